// round 1
// baseline (speedup 1.0000x reference)
#include <cuda_runtime.h>
#include <cuda_bf16.h>

// Problem constants (fixed shapes per metadata):
//   z:        (16, 256, 32, 32) fp32  -> 4,194,304 elems
//   codebook: (2048, 256)       fp32  ->   524,288 elems
//   out:      (16, 256, 32, 32) fp32
#define N_ROWS 16384   // B*H*W tokens
#define DDIM   256
#define KCODES 2048
#define HW     1024    // H*W (stride between consecutive d for a fixed token)

// Scratch (no device mallocs allowed -> __device__ globals)
__device__ float g_cnorm[KCODES];
__device__ float g_znorm[N_ROWS];
__device__ int   g_bestIdx[N_ROWS];

// ---------------------------------------------------------------------------
// ||c_k||^2, sequential over d (mirrors reference sum structure)
// ---------------------------------------------------------------------------
__global__ void cnorm_kernel(const float* __restrict__ cb) {
    int k = blockIdx.x * blockDim.x + threadIdx.x;
    if (k >= KCODES) return;
    const float* row = cb + (size_t)k * DDIM;
    float s = 0.f;
    #pragma unroll 8
    for (int d = 0; d < DDIM; d++) s = __fmaf_rn(row[d], row[d], s);
    g_cnorm[k] = s;
}

// ---------------------------------------------------------------------------
// ||z_n||^2. Token n = b*1024 + p; element d lives at z[(b*256 + d)*1024 + p],
// so thread-per-token with sequential d is fully coalesced across threads.
// ---------------------------------------------------------------------------
__global__ void znorm_kernel(const float* __restrict__ z) {
    int n = blockIdx.x * blockDim.x + threadIdx.x;
    if (n >= N_ROWS) return;
    int b = n >> 10, p = n & 1023;
    const float* zp = z + (size_t)b * DDIM * HW + p;
    float s = 0.f;
    #pragma unroll 8
    for (int d = 0; d < DDIM; d++) {
        float v = zp[(size_t)d * HW];
        s = __fmaf_rn(v, v, s);
    }
    g_znorm[n] = s;
}

// ---------------------------------------------------------------------------
// Main: tiled fp32 "GEMM + running argmin".
// CTA: 128 tokens x 128 codes per K-tile, loop over 16 K-tiles.
// 256 threads as 16x16; each thread owns an 8x8 accumulator tile.
// dist = (znorm + cnorm) - 2*dot  (explicit rn adds, mirrors reference),
// ties -> lowest code index (matches jnp.argmin first-hit).
// ---------------------------------------------------------------------------
#define TM   128
#define TK   128
#define DK   32
#define SPAD 132   // padded smem row (keeps float4 alignment, breaks conflicts)

__global__ void __launch_bounds__(256, 2)
vq_argmin_kernel(const float* __restrict__ z, const float* __restrict__ cb) {
    __shared__ float zs[DK][SPAD];   // zs[d][token]   (d-major, matches z layout)
    __shared__ float cs[DK][SPAD];   // cs[d][code]

    const int t  = threadIdx.x;
    const int tx = t & 15;           // code direction
    const int ty = t >> 4;           // token direction
    const int row0 = blockIdx.x * TM;
    const int b  = row0 >> 10;
    const int p0 = row0 & 1023;      // TM=128 divides 1024 -> tile stays in one b
    const float* zb = z + (size_t)b * DDIM * HW + p0;

    float zn[8];
    #pragma unroll
    for (int i = 0; i < 8; i++) zn[i] = g_znorm[row0 + ty * 8 + i];

    float best[8];
    int   bidx[8];
    #pragma unroll
    for (int i = 0; i < 8; i++) { best[i] = 3.4e38f; bidx[i] = 0; }

    for (int k0 = 0; k0 < KCODES; k0 += TK) {
        float acc[8][8];
        #pragma unroll
        for (int i = 0; i < 8; i++)
            #pragma unroll
            for (int j = 0; j < 8; j++) acc[i][j] = 0.f;

        for (int cd = 0; cd < DDIM; cd += DK) {
            // --- stage z tile: 32 d x 128 tokens, float4 along tokens (coalesced)
            #pragma unroll
            for (int it = 0; it < 4; it++) {
                int s  = t + it * 256;       // 0..1023 float4 slots
                int dd = s >> 5, pv = s & 31;
                float4 v = *reinterpret_cast<const float4*>(
                    zb + (size_t)(cd + dd) * HW + pv * 4);
                *reinterpret_cast<float4*>(&zs[dd][pv * 4]) = v;
            }
            // --- stage c tile: 128 codes x 32 d, float4 along d, transpose to smem
            #pragma unroll
            for (int it = 0; it < 4; it++) {
                int s  = t + it * 256;
                int k  = s >> 3, dv = s & 7;
                float4 v = *reinterpret_cast<const float4*>(
                    cb + (size_t)(k0 + k) * DDIM + cd + dv * 4);
                cs[dv * 4 + 0][k] = v.x;
                cs[dv * 4 + 1][k] = v.y;
                cs[dv * 4 + 2][k] = v.z;
                cs[dv * 4 + 3][k] = v.w;
            }
            __syncthreads();

            #pragma unroll
            for (int dd = 0; dd < DK; dd++) {
                float4 a0 = *reinterpret_cast<const float4*>(&zs[dd][ty * 8]);
                float4 a1 = *reinterpret_cast<const float4*>(&zs[dd][ty * 8 + 4]);
                float4 b0 = *reinterpret_cast<const float4*>(&cs[dd][tx * 8]);
                float4 b1 = *reinterpret_cast<const float4*>(&cs[dd][tx * 8 + 4]);
                float av[8] = {a0.x, a0.y, a0.z, a0.w, a1.x, a1.y, a1.z, a1.w};
                float bv[8] = {b0.x, b0.y, b0.z, b0.w, b1.x, b1.y, b1.z, b1.w};
                #pragma unroll
                for (int i = 0; i < 8; i++)
                    #pragma unroll
                    for (int j = 0; j < 8; j++)
                        acc[i][j] = __fmaf_rn(av[i], bv[j], acc[i][j]);
            }
            __syncthreads();
        }

        // --- fold this K-tile into the running argmin (registers only)
        float cn[8];
        #pragma unroll
        for (int j = 0; j < 8; j++) cn[j] = g_cnorm[k0 + tx * 8 + j];
        #pragma unroll
        for (int i = 0; i < 8; i++) {
            #pragma unroll
            for (int j = 0; j < 8; j++) {
                float dist = __fadd_rn(__fadd_rn(zn[i], cn[j]), -2.0f * acc[i][j]);
                int kk = k0 + tx * 8 + j;
                if (dist < best[i]) { best[i] = dist; bidx[i] = kk; }  // strict <: first index wins
            }
        }
    }

    // --- reduce across the 16 tx threads (one half-warp), lexicographic (dist, idx)
    #pragma unroll
    for (int i = 0; i < 8; i++) {
        float v   = best[i];
        int   idx = bidx[i];
        #pragma unroll
        for (int off = 1; off < 16; off <<= 1) {
            float vo = __shfl_xor_sync(0xffffffffu, v, off);
            int   io = __shfl_xor_sync(0xffffffffu, idx, off);
            if (vo < v || (vo == v && io < idx)) { v = vo; idx = io; }
        }
        if (tx == 0) g_bestIdx[row0 + ty * 8 + i] = idx;
    }
}

// ---------------------------------------------------------------------------
// Gather + straight-through output: out = z + (z_q - z) with explicit rn adds
// (replicates the reference's rounding exactly rather than emitting raw z_q).
// float4 along tokens: coalesced z read + out write; codebook reads hit L2.
// ---------------------------------------------------------------------------
__global__ void gather_kernel(const float* __restrict__ z,
                              const float* __restrict__ cb,
                              float* __restrict__ out) {
    int o4 = blockIdx.x * blockDim.x + threadIdx.x;   // 1,048,576 threads
    int p4 = o4 & 255;
    int d  = (o4 >> 8) & 255;
    int b  = o4 >> 16;
    int p  = p4 * 4;
    int nb = b * HW + p;
    size_t off = ((size_t)(b * DDIM + d)) * HW + p;

    float4 zv = *reinterpret_cast<const float4*>(z + off);
    float q0 = cb[(size_t)g_bestIdx[nb + 0] * DDIM + d];
    float q1 = cb[(size_t)g_bestIdx[nb + 1] * DDIM + d];
    float q2 = cb[(size_t)g_bestIdx[nb + 2] * DDIM + d];
    float q3 = cb[(size_t)g_bestIdx[nb + 3] * DDIM + d];

    float4 r;
    r.x = __fadd_rn(zv.x, __fadd_rn(q0, -zv.x));
    r.y = __fadd_rn(zv.y, __fadd_rn(q1, -zv.y));
    r.z = __fadd_rn(zv.z, __fadd_rn(q2, -zv.z));
    r.w = __fadd_rn(zv.w, __fadd_rn(q3, -zv.w));
    *reinterpret_cast<float4*>(out + off) = r;
}

// ---------------------------------------------------------------------------
extern "C" void kernel_launch(void* const* d_in, const int* in_sizes, int n_in,
                              void* d_out, int out_size) {
    const float* z  = (const float*)d_in[0];   // (16,256,32,32) fp32
    const float* cb = (const float*)d_in[1];   // (2048,256) fp32
    float* out = (float*)d_out;

    cnorm_kernel<<<KCODES / 256, 256>>>(cb);
    znorm_kernel<<<N_ROWS / 256, 256>>>(z);
    vq_argmin_kernel<<<N_ROWS / TM, 256>>>(z, cb);
    gather_kernel<<<(N_ROWS * DDIM / 4) / 256, 256>>>(z, cb, out);
}

// round 2
// speedup vs baseline: 1.3054x; 1.3054x over previous
#include <cuda_runtime.h>
#include <cuda_bf16.h>

// Problem constants (fixed shapes per metadata):
//   z:        (16, 256, 32, 32) fp32  -> 4,194,304 elems
//   codebook: (2048, 256)       fp32  ->   524,288 elems
//   out:      (16, 256, 32, 32) fp32
#define N_ROWS 16384   // B*H*W tokens
#define DDIM   256
#define KCODES 2048
#define HW     1024    // H*W (stride between consecutive d for a fixed token)

// Scratch (no device mallocs allowed -> __device__ globals)
__device__ float g_cnorm[KCODES];
__device__ float g_znorm[N_ROWS];
__device__ int   g_bestIdx[N_ROWS];

// ---------------------------------------------------------------------------
// Packed fp32x2 helpers (Blackwell-only FFMA2 path, PTX fma.rn.f32x2).
// Each lane is an independent fma.rn.f32 -> bitwise identical to scalar chain.
// ---------------------------------------------------------------------------
__device__ __forceinline__ unsigned long long bcast_f32x2(float v) {
    unsigned long long r;
    asm("mov.b64 %0, {%1, %1};" : "=l"(r) : "f"(v));
    return r;
}
__device__ __forceinline__ void ffma2(unsigned long long& d,
                                      unsigned long long a,
                                      unsigned long long b) {
    asm("fma.rn.f32x2 %0, %1, %2, %0;" : "+l"(d) : "l"(a), "l"(b));
}
__device__ __forceinline__ void unpack2(unsigned long long p, float& lo, float& hi) {
    asm("mov.b64 {%0, %1}, %2;" : "=f"(lo), "=f"(hi) : "l"(p));
}

// ---------------------------------------------------------------------------
// ||c_k||^2, sequential over d (mirrors reference sum structure)
// ---------------------------------------------------------------------------
__global__ void cnorm_kernel(const float* __restrict__ cb) {
    int k = blockIdx.x * blockDim.x + threadIdx.x;
    if (k >= KCODES) return;
    const float* row = cb + (size_t)k * DDIM;
    float s = 0.f;
    #pragma unroll 8
    for (int d = 0; d < DDIM; d++) s = __fmaf_rn(row[d], row[d], s);
    g_cnorm[k] = s;
}

// ---------------------------------------------------------------------------
// ||z_n||^2. Token n = b*1024 + p; element d lives at z[(b*256 + d)*1024 + p],
// so thread-per-token with sequential d is fully coalesced across threads.
// ---------------------------------------------------------------------------
__global__ void znorm_kernel(const float* __restrict__ z) {
    int n = blockIdx.x * blockDim.x + threadIdx.x;
    if (n >= N_ROWS) return;
    int b = n >> 10, p = n & 1023;
    const float* zp = z + (size_t)b * DDIM * HW + p;
    float s = 0.f;
    #pragma unroll 8
    for (int d = 0; d < DDIM; d++) {
        float v = zp[(size_t)d * HW];
        s = __fmaf_rn(v, v, s);
    }
    g_znorm[n] = s;
}

// ---------------------------------------------------------------------------
// Main: tiled fp32 "GEMM + running argmin" with packed FFMA2 inner loop.
// CTA: 128 tokens x 128 codes per K-tile, loop over 16 K-tiles.
// 256 threads as 16x16; each thread owns an 8x8 accumulator tile, held as
// 8x4 f32x2 pairs (pairs along the code direction j).
// dist = (znorm + cnorm) - 2*dot  (explicit rn adds, mirrors reference),
// ties -> lowest code index (matches jnp.argmin first-hit).
// ---------------------------------------------------------------------------
#define TM   128
#define TK   128
#define DK   32
#define SPAD 132   // padded smem row: 132*4 = 528 bytes, 16B-divisible

__global__ void __launch_bounds__(256, 2)
vq_argmin_kernel(const float* __restrict__ z, const float* __restrict__ cb) {
    __shared__ float zs[DK][SPAD];   // zs[d][token]   (d-major, matches z layout)
    __shared__ float cs[DK][SPAD];   // cs[d][code]

    const int t  = threadIdx.x;
    const int tx = t & 15;           // code direction
    const int ty = t >> 4;           // token direction
    const int row0 = blockIdx.x * TM;
    const int b  = row0 >> 10;
    const int p0 = row0 & 1023;      // TM=128 divides 1024 -> tile stays in one b
    const float* zb = z + (size_t)b * DDIM * HW + p0;

    float zn[8];
    #pragma unroll
    for (int i = 0; i < 8; i++) zn[i] = g_znorm[row0 + ty * 8 + i];

    float best[8];
    int   bidx[8];
    #pragma unroll
    for (int i = 0; i < 8; i++) { best[i] = 3.4e38f; bidx[i] = 0; }

    for (int k0 = 0; k0 < KCODES; k0 += TK) {
        unsigned long long acc2[8][4];   // (j, j+1) pairs
        #pragma unroll
        for (int i = 0; i < 8; i++)
            #pragma unroll
            for (int j = 0; j < 4; j++) acc2[i][j] = 0ull;

        for (int cd = 0; cd < DDIM; cd += DK) {
            // --- stage z tile: 32 d x 128 tokens, float4 along tokens (coalesced)
            #pragma unroll
            for (int it = 0; it < 4; it++) {
                int s  = t + it * 256;       // 0..1023 float4 slots
                int dd = s >> 5, pv = s & 31;
                float4 v = *reinterpret_cast<const float4*>(
                    zb + (size_t)(cd + dd) * HW + pv * 4);
                *reinterpret_cast<float4*>(&zs[dd][pv * 4]) = v;
            }
            // --- stage c tile: 128 codes x 32 d, float4 along d, transpose to smem
            #pragma unroll
            for (int it = 0; it < 4; it++) {
                int s  = t + it * 256;
                int k  = s >> 3, dv = s & 7;
                float4 v = *reinterpret_cast<const float4*>(
                    cb + (size_t)(k0 + k) * DDIM + cd + dv * 4);
                cs[dv * 4 + 0][k] = v.x;
                cs[dv * 4 + 1][k] = v.y;
                cs[dv * 4 + 2][k] = v.z;
                cs[dv * 4 + 3][k] = v.w;
            }
            __syncthreads();

            #pragma unroll
            for (int dd = 0; dd < DK; dd++) {
                // b side: pairs come for free from 128-bit LDS
                ulonglong2 b01 = *reinterpret_cast<const ulonglong2*>(&cs[dd][tx * 8]);
                ulonglong2 b23 = *reinterpret_cast<const ulonglong2*>(&cs[dd][tx * 8 + 4]);
                // a side: scalar loads, broadcast into both f32x2 lanes
                float4 a0 = *reinterpret_cast<const float4*>(&zs[dd][ty * 8]);
                float4 a1 = *reinterpret_cast<const float4*>(&zs[dd][ty * 8 + 4]);
                float av[8] = {a0.x, a0.y, a0.z, a0.w, a1.x, a1.y, a1.z, a1.w};
                #pragma unroll
                for (int i = 0; i < 8; i++) {
                    unsigned long long ap = bcast_f32x2(av[i]);
                    ffma2(acc2[i][0], ap, b01.x);
                    ffma2(acc2[i][1], ap, b01.y);
                    ffma2(acc2[i][2], ap, b23.x);
                    ffma2(acc2[i][3], ap, b23.y);
                }
            }
            __syncthreads();
        }

        // --- fold this K-tile into the running argmin (registers only)
        float cn[8];
        #pragma unroll
        for (int j = 0; j < 8; j++) cn[j] = g_cnorm[k0 + tx * 8 + j];
        #pragma unroll
        for (int i = 0; i < 8; i++) {
            float accf[8];
            #pragma unroll
            for (int j2 = 0; j2 < 4; j2++)
                unpack2(acc2[i][j2], accf[2 * j2], accf[2 * j2 + 1]);
            #pragma unroll
            for (int j = 0; j < 8; j++) {
                float dist = __fadd_rn(__fadd_rn(zn[i], cn[j]), -2.0f * accf[j]);
                int kk = k0 + tx * 8 + j;
                if (dist < best[i]) { best[i] = dist; bidx[i] = kk; }  // strict <: first index wins
            }
        }
    }

    // --- reduce across the 16 tx threads (one half-warp), lexicographic (dist, idx)
    #pragma unroll
    for (int i = 0; i < 8; i++) {
        float v   = best[i];
        int   idx = bidx[i];
        #pragma unroll
        for (int off = 1; off < 16; off <<= 1) {
            float vo = __shfl_xor_sync(0xffffffffu, v, off);
            int   io = __shfl_xor_sync(0xffffffffu, idx, off);
            if (vo < v || (vo == v && io < idx)) { v = vo; idx = io; }
        }
        if (tx == 0) g_bestIdx[row0 + ty * 8 + i] = idx;
    }
}

// ---------------------------------------------------------------------------
// Gather + straight-through output: out = z + (z_q - z) with explicit rn adds
// (replicates the reference's rounding exactly rather than emitting raw z_q).
// float4 along tokens: coalesced z read + out write; codebook reads hit L2.
// ---------------------------------------------------------------------------
__global__ void gather_kernel(const float* __restrict__ z,
                              const float* __restrict__ cb,
                              float* __restrict__ out) {
    int o4 = blockIdx.x * blockDim.x + threadIdx.x;   // 1,048,576 threads
    int p4 = o4 & 255;
    int d  = (o4 >> 8) & 255;
    int b  = o4 >> 16;
    int p  = p4 * 4;
    int nb = b * HW + p;
    size_t off = ((size_t)(b * DDIM + d)) * HW + p;

    float4 zv = *reinterpret_cast<const float4*>(z + off);
    float q0 = cb[(size_t)g_bestIdx[nb + 0] * DDIM + d];
    float q1 = cb[(size_t)g_bestIdx[nb + 1] * DDIM + d];
    float q2 = cb[(size_t)g_bestIdx[nb + 2] * DDIM + d];
    float q3 = cb[(size_t)g_bestIdx[nb + 3] * DDIM + d];

    float4 r;
    r.x = __fadd_rn(zv.x, __fadd_rn(q0, -zv.x));
    r.y = __fadd_rn(zv.y, __fadd_rn(q1, -zv.y));
    r.z = __fadd_rn(zv.z, __fadd_rn(q2, -zv.z));
    r.w = __fadd_rn(zv.w, __fadd_rn(q3, -zv.w));
    *reinterpret_cast<float4*>(out + off) = r;
}

// ---------------------------------------------------------------------------
extern "C" void kernel_launch(void* const* d_in, const int* in_sizes, int n_in,
                              void* d_out, int out_size) {
    const float* z  = (const float*)d_in[0];   // (16,256,32,32) fp32
    const float* cb = (const float*)d_in[1];   // (2048,256) fp32
    float* out = (float*)d_out;

    cnorm_kernel<<<KCODES / 256, 256>>>(cb);
    znorm_kernel<<<N_ROWS / 256, 256>>>(z);
    vq_argmin_kernel<<<N_ROWS / TM, 256>>>(z, cb);
    gather_kernel<<<(N_ROWS * DDIM / 4) / 256, 256>>>(z, cb, out);
}